// round 2
// baseline (speedup 1.0000x reference)
#include <cuda_runtime.h>
#include <math.h>

// Problem constants
#define Bq   4
#define Sq   2048
#define Nk   2048
#define Dm   1024
#define Hh   16
#define HDim 64
#define LN_EPS 1e-5f
#define QSCALE 0.125f   // HD^-0.5

// Scratch (allocation-free rule: __device__ globals)
__device__ float g_knorm[Bq * Nk * HDim];          // normalized K
__device__ float g_attn [Bq * Sq * Dm];            // attention output (B,S,D)
__device__ float g_xnorm[Bq * Sq * Dm];            // layernormed attention output

// ---------------------------------------------------------------------------
// Kernel 1: K layernorm. One warp per row of 64.
// ---------------------------------------------------------------------------
__global__ void mqa_knorm_kernel(const float* __restrict__ xk,
                                 const float* __restrict__ kw,
                                 const float* __restrict__ kb) {
    int row  = blockIdx.x * 8 + (threadIdx.x >> 5);
    int lane = threadIdx.x & 31;
    const float* src = xk + (size_t)row * HDim;
    float v0 = src[lane], v1 = src[lane + 32];
    float s = v0 + v1;
    #pragma unroll
    for (int o = 16; o; o >>= 1) s += __shfl_xor_sync(0xffffffffu, s, o);
    float mean = s * (1.0f / HDim);
    float d0 = v0 - mean, d1 = v1 - mean;
    float ss = d0 * d0 + d1 * d1;
    #pragma unroll
    for (int o = 16; o; o >>= 1) ss += __shfl_xor_sync(0xffffffffu, ss, o);
    float rstd = rsqrtf(ss * (1.0f / HDim) + LN_EPS);
    float* dst = g_knorm + (size_t)row * HDim;
    dst[lane]      = d0 * rstd * kw[lane]      + kb[lane];
    dst[lane + 32] = d1 * rstd * kw[lane + 32] + kb[lane + 32];
}

// ---------------------------------------------------------------------------
// Kernel 2: fused Q-layernorm + flash attention.
// Grid: (S/64, H, B). 256 threads = 16x16; each thread owns a 4x4 microtile.
// Dynamic smem layout (floats):
//   sQ  [64][65]  (normalized+scaled Q)
//   sKT [64][68]  (K tile transposed: sKT[d][n])
//   sV  [64][64]
//   sP  [64][65]  (probabilities)
// ---------------------------------------------------------------------------
#define FLASH_SMEM_FLOATS (64*65 + 64*68 + 64*64 + 64*65)
#define FLASH_SMEM_BYTES  (FLASH_SMEM_FLOATS * 4)

__global__ void __launch_bounds__(256, 1)
mqa_flash_kernel(const float* __restrict__ xq,
                 const float* __restrict__ xv,
                 const float* __restrict__ qw,
                 const float* __restrict__ qb) {
    extern __shared__ float smem[];
    float* sQ  = smem;                 // stride 65
    float* sKT = sQ  + 64 * 65;        // stride 68
    float* sV  = sKT + 64 * 68;        // stride 64
    float* sP  = sV  + 64 * 64;        // stride 65

    const int b  = blockIdx.z;
    const int h  = blockIdx.y;
    const int s0 = blockIdx.x * 64;
    const int tid = threadIdx.x;
    const int ty  = tid >> 4, tx = tid & 15;
    const int ty4 = ty * 4,  tx4 = tx * 4;

    // Load Q tile (contiguous 64x64 block: q[b,h,s,d] = xq[b*S*D + h*S*HD + s*HD + d])
    const float* qsrc = xq + (size_t)b * Sq * Dm + (size_t)h * Sq * HDim + (size_t)s0 * HDim;
    for (int i = tid * 4; i < 64 * HDim; i += 256 * 4) {
        float4 v = *reinterpret_cast<const float4*>(qsrc + i);
        int r = i >> 6, c = i & 63;
        float* p = sQ + r * 65 + c;
        p[0] = v.x; p[1] = v.y; p[2] = v.z; p[3] = v.w;
    }
    __syncthreads();

    // Q layernorm (per 64-elem row) + scale, in place. Threads 0..63, one row each.
    if (tid < 64) {
        float* rowp = sQ + tid * 65;
        float sum = 0.f;
        #pragma unroll
        for (int d = 0; d < HDim; d++) sum += rowp[d];
        float mean = sum * (1.0f / HDim);
        float ss = 0.f;
        #pragma unroll
        for (int d = 0; d < HDim; d++) { float t = rowp[d] - mean; ss += t * t; }
        float rstd = rsqrtf(ss * (1.0f / HDim) + LN_EPS);
        #pragma unroll
        for (int d = 0; d < HDim; d++)
            rowp[d] = ((rowp[d] - mean) * rstd * qw[d] + qb[d]) * QSCALE;
    }
    __syncthreads();

    float acc[4][4];
    float m_i[4], l_i[4];
    #pragma unroll
    for (int i = 0; i < 4; i++) {
        m_i[i] = -1e30f; l_i[i] = 0.f;
        #pragma unroll
        for (int j = 0; j < 4; j++) acc[i][j] = 0.f;
    }

    const float* kbase = g_knorm + (size_t)b * Nk * HDim;
    const float* vbase = xv      + (size_t)b * Nk * HDim;

    for (int n0 = 0; n0 < Nk; n0 += 64) {
        // Load K tile (transposed into sKT) and V tile
        for (int i = tid * 4; i < 64 * HDim; i += 256 * 4) {
            int r = i >> 6, c = i & 63;
            float4 kv = *reinterpret_cast<const float4*>(kbase + (size_t)(n0 + r) * HDim + c);
            sKT[(c + 0) * 68 + r] = kv.x;
            sKT[(c + 1) * 68 + r] = kv.y;
            sKT[(c + 2) * 68 + r] = kv.z;
            sKT[(c + 3) * 68 + r] = kv.w;
            float4 vv = *reinterpret_cast<const float4*>(vbase + (size_t)(n0 + r) * HDim + c);
            *reinterpret_cast<float4*>(sV + r * 64 + c) = vv;
        }
        __syncthreads();

        // S = Q K^T, 4x4 microtile per thread
        float s[4][4];
        #pragma unroll
        for (int i = 0; i < 4; i++)
            #pragma unroll
            for (int j = 0; j < 4; j++) s[i][j] = 0.f;

        #pragma unroll 4
        for (int d = 0; d < HDim; d++) {
            float a0 = sQ[(ty4 + 0) * 65 + d];
            float a1 = sQ[(ty4 + 1) * 65 + d];
            float a2 = sQ[(ty4 + 2) * 65 + d];
            float a3 = sQ[(ty4 + 3) * 65 + d];
            float4 bb = *reinterpret_cast<const float4*>(sKT + d * 68 + tx4);
            s[0][0] = fmaf(a0, bb.x, s[0][0]); s[0][1] = fmaf(a0, bb.y, s[0][1]);
            s[0][2] = fmaf(a0, bb.z, s[0][2]); s[0][3] = fmaf(a0, bb.w, s[0][3]);
            s[1][0] = fmaf(a1, bb.x, s[1][0]); s[1][1] = fmaf(a1, bb.y, s[1][1]);
            s[1][2] = fmaf(a1, bb.z, s[1][2]); s[1][3] = fmaf(a1, bb.w, s[1][3]);
            s[2][0] = fmaf(a2, bb.x, s[2][0]); s[2][1] = fmaf(a2, bb.y, s[2][1]);
            s[2][2] = fmaf(a2, bb.z, s[2][2]); s[2][3] = fmaf(a2, bb.w, s[2][3]);
            s[3][0] = fmaf(a3, bb.x, s[3][0]); s[3][1] = fmaf(a3, bb.y, s[3][1]);
            s[3][2] = fmaf(a3, bb.z, s[3][2]); s[3][3] = fmaf(a3, bb.w, s[3][3]);
        }

        // Online softmax update (row groups of 16 lanes share a warp half)
        #pragma unroll
        for (int i = 0; i < 4; i++) {
            float mt = fmaxf(fmaxf(s[i][0], s[i][1]), fmaxf(s[i][2], s[i][3]));
            #pragma unroll
            for (int o = 8; o; o >>= 1) mt = fmaxf(mt, __shfl_xor_sync(0xffffffffu, mt, o));
            float mnew = fmaxf(m_i[i], mt);
            float corr = __expf(m_i[i] - mnew);
            float lsum = 0.f;
            #pragma unroll
            for (int j = 0; j < 4; j++) { float p = __expf(s[i][j] - mnew); s[i][j] = p; lsum += p; }
            #pragma unroll
            for (int o = 8; o; o >>= 1) lsum += __shfl_xor_sync(0xffffffffu, lsum, o);
            l_i[i] = l_i[i] * corr + lsum;
            m_i[i] = mnew;
            #pragma unroll
            for (int j = 0; j < 4; j++) acc[i][j] *= corr;
            #pragma unroll
            for (int j = 0; j < 4; j++) sP[(ty4 + i) * 65 + tx4 + j] = s[i][j];
        }
        __syncthreads();

        // O += P @ V
        #pragma unroll 4
        for (int n = 0; n < 64; n++) {
            float p0 = sP[(ty4 + 0) * 65 + n];
            float p1 = sP[(ty4 + 1) * 65 + n];
            float p2 = sP[(ty4 + 2) * 65 + n];
            float p3 = sP[(ty4 + 3) * 65 + n];
            float4 vv = *reinterpret_cast<const float4*>(sV + n * 64 + tx4);
            acc[0][0] = fmaf(p0, vv.x, acc[0][0]); acc[0][1] = fmaf(p0, vv.y, acc[0][1]);
            acc[0][2] = fmaf(p0, vv.z, acc[0][2]); acc[0][3] = fmaf(p0, vv.w, acc[0][3]);
            acc[1][0] = fmaf(p1, vv.x, acc[1][0]); acc[1][1] = fmaf(p1, vv.y, acc[1][1]);
            acc[1][2] = fmaf(p1, vv.z, acc[1][2]); acc[1][3] = fmaf(p1, vv.w, acc[1][3]);
            acc[2][0] = fmaf(p2, vv.x, acc[2][0]); acc[2][1] = fmaf(p2, vv.y, acc[2][1]);
            acc[2][2] = fmaf(p2, vv.z, acc[2][2]); acc[2][3] = fmaf(p2, vv.w, acc[2][3]);
            acc[3][0] = fmaf(p3, vv.x, acc[3][0]); acc[3][1] = fmaf(p3, vv.y, acc[3][1]);
            acc[3][2] = fmaf(p3, vv.z, acc[3][2]); acc[3][3] = fmaf(p3, vv.w, acc[3][3]);
        }
        __syncthreads();
    }

    // Epilogue: normalize by l and write to (B,S,D) layout (transpose folded in)
    float* obase = g_attn + (size_t)b * Sq * Dm + (size_t)s0 * Dm + h * HDim;
    #pragma unroll
    for (int i = 0; i < 4; i++) {
        float inv = 1.0f / l_i[i];
        float4 o;
        o.x = acc[i][0] * inv; o.y = acc[i][1] * inv;
        o.z = acc[i][2] * inv; o.w = acc[i][3] * inv;
        *reinterpret_cast<float4*>(obase + (size_t)(ty4 + i) * Dm + tx4) = o;
    }
}

// ---------------------------------------------------------------------------
// Kernel 3: output layernorm over D=1024. One block (256 thr) per row.
// ---------------------------------------------------------------------------
__global__ void mqa_lnorm_kernel(const float* __restrict__ nw,
                                 const float* __restrict__ nb) {
    __shared__ float red[8];
    __shared__ float s_mean, s_rstd;
    int row = blockIdx.x;
    int tid = threadIdx.x;
    const float4* src = reinterpret_cast<const float4*>(g_attn + (size_t)row * Dm);
    float4 v = src[tid];
    float s = v.x + v.y + v.z + v.w;
    #pragma unroll
    for (int o = 16; o; o >>= 1) s += __shfl_xor_sync(0xffffffffu, s, o);
    if ((tid & 31) == 0) red[tid >> 5] = s;
    __syncthreads();
    if (tid == 0) {
        float t = 0.f;
        #pragma unroll
        for (int w = 0; w < 8; w++) t += red[w];
        s_mean = t * (1.0f / Dm);
    }
    __syncthreads();
    float mean = s_mean;
    float dx = v.x - mean, dy = v.y - mean, dz = v.z - mean, dw = v.w - mean;
    float ss = dx * dx + dy * dy + dz * dz + dw * dw;
    #pragma unroll
    for (int o = 16; o; o >>= 1) ss += __shfl_xor_sync(0xffffffffu, ss, o);
    if ((tid & 31) == 0) red[tid >> 5] = ss;
    __syncthreads();
    if (tid == 0) {
        float t = 0.f;
        #pragma unroll
        for (int w = 0; w < 8; w++) t += red[w];
        s_rstd = rsqrtf(t * (1.0f / Dm) + LN_EPS);
    }
    __syncthreads();
    float rstd = s_rstd;
    float4 w4 = reinterpret_cast<const float4*>(nw)[tid];
    float4 b4 = reinterpret_cast<const float4*>(nb)[tid];
    float4 o;
    o.x = dx * rstd * w4.x + b4.x;
    o.y = dy * rstd * w4.y + b4.y;
    o.z = dz * rstd * w4.z + b4.z;
    o.w = dw * rstd * w4.w + b4.w;
    reinterpret_cast<float4*>(g_xnorm + (size_t)row * Dm)[tid] = o;
}

// ---------------------------------------------------------------------------
// Kernel 4: projection GEMM. out[m][n] = sum_k xnorm[m][k] * W[n][k]
// M=8192, N=1024, K=1024. BM=BN=64, BK=16, 256 thr, 4x4 microtile.
// ---------------------------------------------------------------------------
__global__ void __launch_bounds__(256, 1)
mqa_proj_kernel(const float* __restrict__ W, float* __restrict__ out) {
    __shared__ float sXT[16 * 68];   // sXT[c][r] = X[m0+r][k0+c]
    __shared__ float sWT[16 * 68];   // sWT[c][r] = W[n0+r][k0+c]
    const int m0 = blockIdx.y * 64, n0 = blockIdx.x * 64;
    const int tid = threadIdx.x;
    const int ty4 = (tid >> 4) * 4, tx4 = (tid & 15) * 4;
    const float* X = g_xnorm;
    float acc[4][4];
    #pragma unroll
    for (int i = 0; i < 4; i++)
        #pragma unroll
        for (int j = 0; j < 4; j++) acc[i][j] = 0.f;

    for (int k0 = 0; k0 < Dm; k0 += 16) {
        for (int i = tid; i < 64 * 16; i += 256) {
            int r = i >> 4, c = i & 15;
            sXT[c * 68 + r] = X[(size_t)(m0 + r) * Dm + k0 + c];
            sWT[c * 68 + r] = W[(size_t)(n0 + r) * Dm + k0 + c];
        }
        __syncthreads();
        #pragma unroll
        for (int kk = 0; kk < 16; kk++) {
            float4 a  = *reinterpret_cast<const float4*>(sXT + kk * 68 + ty4);
            float4 bb = *reinterpret_cast<const float4*>(sWT + kk * 68 + tx4);
            acc[0][0] = fmaf(a.x, bb.x, acc[0][0]); acc[0][1] = fmaf(a.x, bb.y, acc[0][1]);
            acc[0][2] = fmaf(a.x, bb.z, acc[0][2]); acc[0][3] = fmaf(a.x, bb.w, acc[0][3]);
            acc[1][0] = fmaf(a.y, bb.x, acc[1][0]); acc[1][1] = fmaf(a.y, bb.y, acc[1][1]);
            acc[1][2] = fmaf(a.y, bb.z, acc[1][2]); acc[1][3] = fmaf(a.y, bb.w, acc[1][3]);
            acc[2][0] = fmaf(a.z, bb.x, acc[2][0]); acc[2][1] = fmaf(a.z, bb.y, acc[2][1]);
            acc[2][2] = fmaf(a.z, bb.z, acc[2][2]); acc[2][3] = fmaf(a.z, bb.w, acc[2][3]);
            acc[3][0] = fmaf(a.w, bb.x, acc[3][0]); acc[3][1] = fmaf(a.w, bb.y, acc[3][1]);
            acc[3][2] = fmaf(a.w, bb.z, acc[3][2]); acc[3][3] = fmaf(a.w, bb.w, acc[3][3]);
        }
        __syncthreads();
    }

    #pragma unroll
    for (int i = 0; i < 4; i++) {
        float4 o = { acc[i][0], acc[i][1], acc[i][2], acc[i][3] };
        *reinterpret_cast<float4*>(out + (size_t)(m0 + ty4 + i) * Dm + n0 + tx4) = o;
    }
}

// ---------------------------------------------------------------------------
extern "C" void kernel_launch(void* const* d_in, const int* in_sizes, int n_in,
                              void* d_out, int out_size) {
    const float* x_q    = (const float*)d_in[0];
    const float* x_k    = (const float*)d_in[1];
    const float* x_v    = (const float*)d_in[2];
    const float* qn_w   = (const float*)d_in[3];
    const float* qn_b   = (const float*)d_in[4];
    const float* kn_w   = (const float*)d_in[5];
    const float* kn_b   = (const float*)d_in[6];
    const float* n_w    = (const float*)d_in[7];
    const float* n_b    = (const float*)d_in[8];
    const float* proj_w = (const float*)d_in[9];
    float* out = (float*)d_out;

    cudaFuncSetAttribute(mqa_flash_kernel,
                         cudaFuncAttributeMaxDynamicSharedMemorySize,
                         FLASH_SMEM_BYTES);

    mqa_knorm_kernel<<<(Bq * Nk) / 8, 256>>>(x_k, kn_w, kn_b);
    mqa_flash_kernel<<<dim3(Sq / 64, Hh, Bq), 256, FLASH_SMEM_BYTES>>>(x_q, x_v, qn_w, qn_b);
    mqa_lnorm_kernel<<<Bq * Sq, 256>>>(n_w, n_b);
    mqa_proj_kernel<<<dim3(Dm / 64, (Bq * Sq) / 64), 256>>>(proj_w, out);
}

// round 17
// speedup vs baseline: 2.4981x; 2.4981x over previous
#include <cuda_runtime.h>
#include <math.h>
#include <stdint.h>

// Problem constants
#define Bq   4
#define Sq   2048
#define Nk   2048
#define Dm   1024
#define Hh   16
#define HDim 64
#define LN_EPS 1e-5f
#define QSCALE 0.125f   // HD^-0.5

// Scratch (allocation-free rule: __device__ globals)
__device__ float g_knorm[Bq * Nk * HDim];          // normalized K
__device__ float g_attn [Bq * Sq * Dm];            // attention output (B,S,D)
__device__ float g_xnorm[Bq * Sq * Dm];            // layernormed attention output

// ---------------------------------------------------------------------------
// tf32 helpers
// ---------------------------------------------------------------------------
__device__ __forceinline__ unsigned f2tf(float f) {
    unsigned u;
    asm("cvt.rna.tf32.f32 %0, %1;" : "=r"(u) : "f"(f));
    return u;
}

__device__ __forceinline__ void mma_tf32(float* c,
                                         unsigned a0, unsigned a1, unsigned a2, unsigned a3,
                                         unsigned b0, unsigned b1) {
    asm volatile(
        "mma.sync.aligned.m16n8k8.row.col.f32.tf32.tf32.f32 "
        "{%0,%1,%2,%3}, {%4,%5,%6,%7}, {%8,%9}, {%0,%1,%2,%3};"
        : "+f"(c[0]), "+f"(c[1]), "+f"(c[2]), "+f"(c[3])
        : "r"(a0), "r"(a1), "r"(a2), "r"(a3), "r"(b0), "r"(b1));
}

// ---------------------------------------------------------------------------
// Kernel 1: K layernorm. One warp per row of 64.
// ---------------------------------------------------------------------------
__global__ void mqa_knorm_kernel(const float* __restrict__ xk,
                                 const float* __restrict__ kw,
                                 const float* __restrict__ kb) {
    int row  = blockIdx.x * 8 + (threadIdx.x >> 5);
    int lane = threadIdx.x & 31;
    const float* src = xk + (size_t)row * HDim;
    float v0 = src[lane], v1 = src[lane + 32];
    float s = v0 + v1;
    #pragma unroll
    for (int o = 16; o; o >>= 1) s += __shfl_xor_sync(0xffffffffu, s, o);
    float mean = s * (1.0f / HDim);
    float d0 = v0 - mean, d1 = v1 - mean;
    float ss = d0 * d0 + d1 * d1;
    #pragma unroll
    for (int o = 16; o; o >>= 1) ss += __shfl_xor_sync(0xffffffffu, ss, o);
    float rstd = rsqrtf(ss * (1.0f / HDim) + LN_EPS);
    float* dst = g_knorm + (size_t)row * HDim;
    dst[lane]      = d0 * rstd * kw[lane]      + kb[lane];
    dst[lane + 32] = d1 * rstd * kw[lane + 32] + kb[lane + 32];
}

// ---------------------------------------------------------------------------
// Kernel 2: fused Q-layernorm + flash attention, tf32 tensor-core version.
// Grid: (S/64, H, B). 256 threads = 8 warps.
// Per KV tile of 64:
//   QK^T: warp w computes S[16 rows (w&3), 32 cols (w>>2)] via mma -> sS
//   softmax: 4 threads/row online update (m, l, corr in smem), P->sP (tf32)
//   PV: warp w computes O[16 rows (w&3), 32 d (w>>2)] += P @ V (mma), O in regs
// Smem strides chosen for conflict-free fragment loads.
// ---------------------------------------------------------------------------
#define FSTR 68
#define VSTR 72
#define FLASH_SMEM_BYTES ((64*FSTR /*Qf*/ + 64*FSTR /*K*/ + 64*VSTR /*V*/ \
                         + 64*FSTR /*S*/ + 64*FSTR /*P*/ + 192) * 4)

__global__ void __launch_bounds__(256, 1)
mqa_flash_kernel(const float* __restrict__ xq,
                 const float* __restrict__ xv,
                 const float* __restrict__ qw,
                 const float* __restrict__ qb) {
    extern __shared__ float smem[];
    float*    sQf = smem;                                   // [64][FSTR] fp32
    unsigned* sK  = (unsigned*)(smem + 64 * FSTR);          // [64][FSTR] tf32
    unsigned* sV  = sK + 64 * FSTR;                         // [64][VSTR] tf32
    float*    sS  = (float*)(sV + 64 * VSTR);               // [64][FSTR] fp32 scores
    unsigned* sP  = (unsigned*)(sS + 64 * FSTR);            // [64][FSTR] tf32 probs
    float*    sM  = (float*)(sP + 64 * FSTR);               // [64]
    float*    sL  = sM + 64;                                // [64]
    float*    sC  = sL + 64;                                // [64] corr

    const int b   = blockIdx.z;
    const int h   = blockIdx.y;
    const int s0  = blockIdx.x * 64;
    const int tid = threadIdx.x;
    const int w   = tid >> 5;
    const int lane = tid & 31;
    const int g   = lane >> 2;      // groupID 0..7
    const int t   = lane & 3;       // threadID_in_group 0..3
    const int qr  = (w & 3) * 16;   // row block of this warp
    const int half = (w >> 2) * 32; // col half (S cols / d cols)

    // ---- Load Q tile (contiguous: q[b,h,s,d] = xq[b*S*D + h*S*HD + s*HD + d])
    const float* qsrc = xq + (size_t)b * Sq * Dm + (size_t)h * Sq * HDim + (size_t)s0 * HDim;
    for (int i = tid * 4; i < 64 * HDim; i += 256 * 4) {
        float4 v = *reinterpret_cast<const float4*>(qsrc + i);
        int r = i >> 6, c = i & 63;
        float* p = sQf + r * FSTR + c;
        p[0] = v.x; p[1] = v.y; p[2] = v.z; p[3] = v.w;
    }
    __syncthreads();

    // ---- Q layernorm + scale (one thread per row), init m/l state
    if (tid < 64) {
        float* rowp = sQf + tid * FSTR;
        float sum = 0.f;
        #pragma unroll
        for (int d = 0; d < HDim; d++) sum += rowp[d];
        float mean = sum * (1.0f / HDim);
        float ss = 0.f;
        #pragma unroll
        for (int d = 0; d < HDim; d++) { float x = rowp[d] - mean; ss += x * x; }
        float rstd = rsqrtf(ss * (1.0f / HDim) + LN_EPS);
        #pragma unroll
        for (int d = 0; d < HDim; d++)
            rowp[d] = ((rowp[d] - mean) * rstd * qw[d] + qb[d]) * QSCALE;
        sM[tid] = -1e30f;
        sL[tid] = 0.f;
    }
    __syncthreads();

    // ---- Hoist Q fragments (rows qr..qr+15, all 64 k) into registers
    unsigned qA[8][4];
    #pragma unroll
    for (int kt = 0; kt < 8; kt++) {
        qA[kt][0] = f2tf(sQf[(qr + g)     * FSTR + kt * 8 + t]);
        qA[kt][1] = f2tf(sQf[(qr + g + 8) * FSTR + kt * 8 + t]);
        qA[kt][2] = f2tf(sQf[(qr + g)     * FSTR + kt * 8 + t + 4]);
        qA[kt][3] = f2tf(sQf[(qr + g + 8) * FSTR + kt * 8 + t + 4]);
    }

    float oc[4][4];
    #pragma unroll
    for (int i = 0; i < 4; i++)
        #pragma unroll
        for (int j = 0; j < 4; j++) oc[i][j] = 0.f;

    const float* kbase = g_knorm + (size_t)b * Nk * HDim;
    const float* vbase = xv      + (size_t)b * Nk * HDim;

    for (int n0 = 0; n0 < Nk; n0 += 64) {
        __syncthreads();   // prev iteration fully consumed sK/sV/sS/sP

        // ---- Load K and V tiles, converting to tf32
        for (int i = tid * 4; i < 64 * HDim; i += 256 * 4) {
            int r = i >> 6, c = i & 63;
            float4 kv = *reinterpret_cast<const float4*>(kbase + (size_t)(n0 + r) * HDim + c);
            uint4 ku = { f2tf(kv.x), f2tf(kv.y), f2tf(kv.z), f2tf(kv.w) };
            *reinterpret_cast<uint4*>(sK + r * FSTR + c) = ku;
            float4 vv = *reinterpret_cast<const float4*>(vbase + (size_t)(n0 + r) * HDim + c);
            uint4 vu = { f2tf(vv.x), f2tf(vv.y), f2tf(vv.z), f2tf(vv.w) };
            *reinterpret_cast<uint4*>(sV + r * VSTR + c) = vu;
        }
        __syncthreads();

        // ---- S = Q K^T for this warp's 16x32 patch
        float sc[4][4];
        #pragma unroll
        for (int nt = 0; nt < 4; nt++)
            #pragma unroll
            for (int j = 0; j < 4; j++) sc[nt][j] = 0.f;

        #pragma unroll
        for (int kt = 0; kt < 8; kt++) {
            #pragma unroll
            for (int nt = 0; nt < 4; nt++) {
                int n = half + nt * 8 + g;
                unsigned b0 = sK[n * FSTR + kt * 8 + t];
                unsigned b1 = sK[n * FSTR + kt * 8 + t + 4];
                mma_tf32(sc[nt], qA[kt][0], qA[kt][1], qA[kt][2], qA[kt][3], b0, b1);
            }
        }
        #pragma unroll
        for (int nt = 0; nt < 4; nt++) {
            int base = (qr + g) * FSTR + half + nt * 8 + 2 * t;
            *reinterpret_cast<float2*>(sS + base)            = make_float2(sc[nt][0], sc[nt][1]);
            *reinterpret_cast<float2*>(sS + base + 8 * FSTR) = make_float2(sc[nt][2], sc[nt][3]);
        }
        __syncthreads();

        // ---- Online softmax: thread handles 16 cols of one row (4 thr/row)
        {
            int row = tid >> 2;
            int seg = (tid & 3) * 16;
            const float* rp = sS + row * FSTR + seg;
            float4 x0 = *reinterpret_cast<const float4*>(rp);
            float4 x1 = *reinterpret_cast<const float4*>(rp + 4);
            float4 x2 = *reinterpret_cast<const float4*>(rp + 8);
            float4 x3 = *reinterpret_cast<const float4*>(rp + 12);
            float mx = fmaxf(fmaxf(fmaxf(x0.x, x0.y), fmaxf(x0.z, x0.w)),
                             fmaxf(fmaxf(x1.x, x1.y), fmaxf(x1.z, x1.w)));
            mx = fmaxf(mx, fmaxf(fmaxf(fmaxf(x2.x, x2.y), fmaxf(x2.z, x2.w)),
                                 fmaxf(fmaxf(x3.x, x3.y), fmaxf(x3.z, x3.w))));
            mx = fmaxf(mx, __shfl_xor_sync(0xffffffffu, mx, 1));
            mx = fmaxf(mx, __shfl_xor_sync(0xffffffffu, mx, 2));
            float mprev = sM[row];
            float mnew  = fmaxf(mprev, mx);
            float corr  = __expf(mprev - mnew);
            float p[16];
            p[0]=__expf(x0.x-mnew); p[1]=__expf(x0.y-mnew); p[2]=__expf(x0.z-mnew); p[3]=__expf(x0.w-mnew);
            p[4]=__expf(x1.x-mnew); p[5]=__expf(x1.y-mnew); p[6]=__expf(x1.z-mnew); p[7]=__expf(x1.w-mnew);
            p[8]=__expf(x2.x-mnew); p[9]=__expf(x2.y-mnew); p[10]=__expf(x2.z-mnew); p[11]=__expf(x2.w-mnew);
            p[12]=__expf(x3.x-mnew); p[13]=__expf(x3.y-mnew); p[14]=__expf(x3.z-mnew); p[15]=__expf(x3.w-mnew);
            float ls = 0.f;
            #pragma unroll
            for (int j = 0; j < 16; j++) ls += p[j];
            ls += __shfl_xor_sync(0xffffffffu, ls, 1);
            ls += __shfl_xor_sync(0xffffffffu, ls, 2);
            unsigned* pw = sP + row * FSTR + seg;
            #pragma unroll
            for (int q4 = 0; q4 < 4; q4++) {
                uint4 u = { f2tf(p[q4*4]), f2tf(p[q4*4+1]), f2tf(p[q4*4+2]), f2tf(p[q4*4+3]) };
                *reinterpret_cast<uint4*>(pw + q4 * 4) = u;
            }
            if ((tid & 3) == 0) {
                sM[row] = mnew;
                sL[row] = sL[row] * corr + ls;
                sC[row] = corr;
            }
        }
        __syncthreads();

        // ---- O = O*corr + P @ V for this warp's 16x32 d patch
        float c0 = sC[qr + g];
        float c1 = sC[qr + g + 8];
        #pragma unroll
        for (int dt = 0; dt < 4; dt++) {
            oc[dt][0] *= c0; oc[dt][1] *= c0;
            oc[dt][2] *= c1; oc[dt][3] *= c1;
        }
        #pragma unroll
        for (int kt = 0; kt < 8; kt++) {
            unsigned a0 = sP[(qr + g)     * FSTR + kt * 8 + t];
            unsigned a1 = sP[(qr + g + 8) * FSTR + kt * 8 + t];
            unsigned a2 = sP[(qr + g)     * FSTR + kt * 8 + t + 4];
            unsigned a3 = sP[(qr + g + 8) * FSTR + kt * 8 + t + 4];
            #pragma unroll
            for (int dt = 0; dt < 4; dt++) {
                int dcol = half + dt * 8 + g;
                unsigned b0 = sV[(kt * 8 + t)     * VSTR + dcol];
                unsigned b1 = sV[(kt * 8 + t + 4) * VSTR + dcol];
                mma_tf32(oc[dt], a0, a1, a2, a3, b0, b1);
            }
        }
    }
    __syncthreads();

    // ---- Epilogue: normalize and write to (B,S,D) with head-transpose folded
    float inv0 = 1.0f / sL[qr + g];
    float inv1 = 1.0f / sL[qr + g + 8];
    float* ob = g_attn + (size_t)b * Sq * Dm + (size_t)(s0 + qr + g) * Dm + h * HDim;
    #pragma unroll
    for (int dt = 0; dt < 4; dt++) {
        int col = half + dt * 8 + 2 * t;
        *reinterpret_cast<float2*>(ob + col) =
            make_float2(oc[dt][0] * inv0, oc[dt][1] * inv0);
        *reinterpret_cast<float2*>(ob + 8 * Dm + col) =
            make_float2(oc[dt][2] * inv1, oc[dt][3] * inv1);
    }
}

// ---------------------------------------------------------------------------
// Kernel 3: output layernorm over D=1024. One block (256 thr) per row.
// ---------------------------------------------------------------------------
__global__ void mqa_lnorm_kernel(const float* __restrict__ nw,
                                 const float* __restrict__ nb) {
    __shared__ float red[8];
    __shared__ float s_mean, s_rstd;
    int row = blockIdx.x;
    int tid = threadIdx.x;
    const float4* src = reinterpret_cast<const float4*>(g_attn + (size_t)row * Dm);
    float4 v = src[tid];
    float s = v.x + v.y + v.z + v.w;
    #pragma unroll
    for (int o = 16; o; o >>= 1) s += __shfl_xor_sync(0xffffffffu, s, o);
    if ((tid & 31) == 0) red[tid >> 5] = s;
    __syncthreads();
    if (tid == 0) {
        float tt = 0.f;
        #pragma unroll
        for (int q = 0; q < 8; q++) tt += red[q];
        s_mean = tt * (1.0f / Dm);
    }
    __syncthreads();
    float mean = s_mean;
    float dx = v.x - mean, dy = v.y - mean, dz = v.z - mean, dw = v.w - mean;
    float ss = dx * dx + dy * dy + dz * dz + dw * dw;
    #pragma unroll
    for (int o = 16; o; o >>= 1) ss += __shfl_xor_sync(0xffffffffu, ss, o);
    if ((tid & 31) == 0) red[tid >> 5] = ss;
    __syncthreads();
    if (tid == 0) {
        float tt = 0.f;
        #pragma unroll
        for (int q = 0; q < 8; q++) tt += red[q];
        s_rstd = rsqrtf(tt * (1.0f / Dm) + LN_EPS);
    }
    __syncthreads();
    float rstd = s_rstd;
    float4 w4 = reinterpret_cast<const float4*>(nw)[tid];
    float4 b4 = reinterpret_cast<const float4*>(nb)[tid];
    float4 o;
    o.x = dx * rstd * w4.x + b4.x;
    o.y = dy * rstd * w4.y + b4.y;
    o.z = dz * rstd * w4.z + b4.z;
    o.w = dw * rstd * w4.w + b4.w;
    reinterpret_cast<float4*>(g_xnorm + (size_t)row * Dm)[tid] = o;
}

// ---------------------------------------------------------------------------
// Kernel 4: projection GEMM via tf32 mma. out[m][n] = sum_k X[m][k] W[n][k]
// Block tile 128x64, BK=32, 256 thr = 8 warps; warp -> 16 rows x 64 cols.
// ---------------------------------------------------------------------------
#define PSTR 36
__global__ void __launch_bounds__(256, 1)
mqa_proj_kernel(const float* __restrict__ W, float* __restrict__ out) {
    __shared__ unsigned sX[128 * PSTR];
    __shared__ unsigned sW[64 * PSTR];
    const int m0 = blockIdx.y * 128, n0 = blockIdx.x * 64;
    const int tid = threadIdx.x;
    const int w = tid >> 5;
    const int lane = tid & 31;
    const int g = lane >> 2, t = lane & 3;
    const int mr = w * 16;
    const float* X = g_xnorm;

    float oc[8][4];
    #pragma unroll
    for (int i = 0; i < 8; i++)
        #pragma unroll
        for (int j = 0; j < 4; j++) oc[i][j] = 0.f;

    const int lr = tid >> 3;          // 0..31
    const int lc = (tid & 7) * 4;     // 0..28

    for (int k0 = 0; k0 < Dm; k0 += 32) {
        #pragma unroll
        for (int p = 0; p < 4; p++) {
            int r = lr + p * 32;
            float4 v = *reinterpret_cast<const float4*>(X + (size_t)(m0 + r) * Dm + k0 + lc);
            uint4 u = { f2tf(v.x), f2tf(v.y), f2tf(v.z), f2tf(v.w) };
            *reinterpret_cast<uint4*>(sX + r * PSTR + lc) = u;
        }
        #pragma unroll
        for (int p = 0; p < 2; p++) {
            int r = lr + p * 32;
            float4 v = *reinterpret_cast<const float4*>(W + (size_t)(n0 + r) * Dm + k0 + lc);
            uint4 u = { f2tf(v.x), f2tf(v.y), f2tf(v.z), f2tf(v.w) };
            *reinterpret_cast<uint4*>(sW + r * PSTR + lc) = u;
        }
        __syncthreads();

        #pragma unroll
        for (int kt = 0; kt < 4; kt++) {
            unsigned a0 = sX[(mr + g)     * PSTR + kt * 8 + t];
            unsigned a1 = sX[(mr + g + 8) * PSTR + kt * 8 + t];
            unsigned a2 = sX[(mr + g)     * PSTR + kt * 8 + t + 4];
            unsigned a3 = sX[(mr + g + 8) * PSTR + kt * 8 + t + 4];
            #pragma unroll
            for (int nt = 0; nt < 8; nt++) {
                unsigned b0 = sW[(nt * 8 + g) * PSTR + kt * 8 + t];
                unsigned b1 = sW[(nt * 8 + g) * PSTR + kt * 8 + t + 4];
                mma_tf32(oc[nt], a0, a1, a2, a3, b0, b1);
            }
        }
        __syncthreads();
    }

    float* ob = out + (size_t)(m0 + mr + g) * Dm + n0;
    #pragma unroll
    for (int nt = 0; nt < 8; nt++) {
        int col = nt * 8 + 2 * t;
        *reinterpret_cast<float2*>(ob + col)          = make_float2(oc[nt][0], oc[nt][1]);
        *reinterpret_cast<float2*>(ob + 8 * Dm + col) = make_float2(oc[nt][2], oc[nt][3]);
    }
}

// ---------------------------------------------------------------------------
extern "C" void kernel_launch(void* const* d_in, const int* in_sizes, int n_in,
                              void* d_out, int out_size) {
    const float* x_q    = (const float*)d_in[0];
    const float* x_k    = (const float*)d_in[1];
    const float* x_v    = (const float*)d_in[2];
    const float* qn_w   = (const float*)d_in[3];
    const float* qn_b   = (const float*)d_in[4];
    const float* kn_w   = (const float*)d_in[5];
    const float* kn_b   = (const float*)d_in[6];
    const float* n_w    = (const float*)d_in[7];
    const float* n_b    = (const float*)d_in[8];
    const float* proj_w = (const float*)d_in[9];
    float* out = (float*)d_out;

    cudaFuncSetAttribute(mqa_flash_kernel,
                         cudaFuncAttributeMaxDynamicSharedMemorySize,
                         FLASH_SMEM_BYTES);

    mqa_knorm_kernel<<<(Bq * Nk) / 8, 256>>>(x_k, kn_w, kn_b);
    mqa_flash_kernel<<<dim3(Sq / 64, Hh, Bq), 256, FLASH_SMEM_BYTES>>>(x_q, x_v, qn_w, qn_b);
    mqa_lnorm_kernel<<<Bq * Sq, 256>>>(n_w, n_b);
    mqa_proj_kernel<<<dim3(Dm / 64, (Bq * Sq) / 128), 256>>>(proj_w, out);
}